// round 3
// baseline (speedup 1.0000x reference)
#include <cuda_runtime.h>
#include <cuda_bf16.h>
#include <cstdint>

#define BB 4096
#define MM 327
#define NN 800
#define NB (BB*NN)              // 3,276,800 per state buffer
#define FEAT (BB*32*NN)         // 104,857,600 per feature buffer
#define FEAT_STRIDE (32*NN)     // 25600 per image
#define PADC 44
#define PADSZ (22*44)           // 968 floats per padded channel

// ---------------- device scratch (static, allowed) ----------------
__device__ float g_PhiTPhi[NN*NN];
__device__ float g_PhiTb[NB];
__device__ float g_Xbuf[2*NB];
__device__ float g_Lbuf[2*NB];
__device__ float g_zerobuf[NB];
__device__ float g_zflat[NB];
__device__ float g_hatx[NB];
__device__ float g_gemm[NB];
__device__ float g_fA[FEAT];
__device__ float g_fB[FEAT];

// ---------------- small GEMMs ----------------

// C[I,J] = sum_k A[k,i] * B[k,j]   (A,B row-major [K, ld]); used for PhiTPhi = W^T W
__global__ __launch_bounds__(256) void gemm_AtB(const float* __restrict__ A,
                                                const float* __restrict__ B,
                                                float* __restrict__ C,
                                                int K, int I, int J)
{
    __shared__ float As[16][68];
    __shared__ float Bs[16][68];
    int tid = threadIdx.x;
    int tx = tid & 15, ty = tid >> 4;
    int i0 = blockIdx.y * 64, j0 = blockIdx.x * 64;
    float acc[4][4];
#pragma unroll
    for (int a = 0; a < 4; a++)
#pragma unroll
        for (int b = 0; b < 4; b++) acc[a][b] = 0.f;

    int kr = tid >> 4, c4 = (tid & 15) * 4;
    for (int k0 = 0; k0 < K; k0 += 16) {
        bool kv = (k0 + kr) < K;
#pragma unroll
        for (int j = 0; j < 4; j++) {
            int ii = i0 + c4 + j;
            As[kr][c4 + j] = (kv && ii < I) ? A[(size_t)(k0 + kr) * I + ii] : 0.f;
            int jj = j0 + c4 + j;
            Bs[kr][c4 + j] = (kv && jj < J) ? B[(size_t)(k0 + kr) * J + jj] : 0.f;
        }
        __syncthreads();
#pragma unroll
        for (int kk = 0; kk < 16; kk++) {
            float a[4], b[4];
#pragma unroll
            for (int i = 0; i < 4; i++) a[i] = As[kk][ty * 4 + i];
#pragma unroll
            for (int j = 0; j < 4; j++) b[j] = Bs[kk][tx * 4 + j];
#pragma unroll
            for (int i = 0; i < 4; i++)
#pragma unroll
                for (int j = 0; j < 4; j++) acc[i][j] += a[i] * b[j];
        }
        __syncthreads();
    }
#pragma unroll
    for (int i = 0; i < 4; i++) {
        int r = i0 + ty * 4 + i;
        if (r < I) {
#pragma unroll
            for (int j = 0; j < 4; j++) {
                int n = j0 + tx * 4 + j;
                if (n < J) C[(size_t)r * J + n] = acc[i][j];
            }
        }
    }
}

// C[M,N] = A[M,K] * B[K,N]  (row-major). M must be multiple of 64.
__global__ __launch_bounds__(256) void gemm_AB(const float* __restrict__ A,
                                               const float* __restrict__ B,
                                               float* __restrict__ C,
                                               int M, int K, int N)
{
    __shared__ float As[16][68];
    __shared__ float Bs[16][68];
    int tid = threadIdx.x;
    int tx = tid & 15, ty = tid >> 4;
    int row0 = blockIdx.y * 64, n0 = blockIdx.x * 64;
    float acc[4][4];
#pragma unroll
    for (int a = 0; a < 4; a++)
#pragma unroll
        for (int b = 0; b < 4; b++) acc[a][b] = 0.f;

    int rowA = tid >> 2, kq = tid & 3;
    int kr = tid >> 4, nc = (tid & 15) * 4;
    for (int k0 = 0; k0 < K; k0 += 16) {
#pragma unroll
        for (int j = 0; j < 4; j++) {
            int k = k0 + kq * 4 + j;
            As[kq * 4 + j][rowA] = (k < K) ? A[(size_t)(row0 + rowA) * K + k] : 0.f;
        }
#pragma unroll
        for (int j = 0; j < 4; j++) {
            int n = n0 + nc + j;
            Bs[kr][nc + j] = ((k0 + kr) < K && n < N) ? B[(size_t)(k0 + kr) * N + n] : 0.f;
        }
        __syncthreads();
#pragma unroll
        for (int kk = 0; kk < 16; kk++) {
            float a[4], b[4];
#pragma unroll
            for (int i = 0; i < 4; i++) a[i] = As[kk][ty * 4 + i];
#pragma unroll
            for (int j = 0; j < 4; j++) b[j] = Bs[kk][tx * 4 + j];
#pragma unroll
            for (int i = 0; i < 4; i++)
#pragma unroll
                for (int j = 0; j < 4; j++) acc[i][j] += a[i] * b[j];
        }
        __syncthreads();
    }
#pragma unroll
    for (int i = 0; i < 4; i++) {
        int r = row0 + ty * 4 + i;
#pragma unroll
        for (int j = 0; j < 4; j++) {
            int n = n0 + tx * 4 + j;
            if (n < N) C[(size_t)r * N + n] = acc[i][j];
        }
    }
}

// Wloss = W @ W^T - I, [327,327], K=800
__global__ void k_wloss(const float* __restrict__ W, float* __restrict__ C)
{
    __shared__ float sA[16][17];
    __shared__ float sB[16][17];
    int tx = threadIdx.x, ty = threadIdx.y;
    int i0 = blockIdx.y * 16, j0 = blockIdx.x * 16;
    float acc = 0.f;
    for (int k0 = 0; k0 < 800; k0 += 16) {
        sA[ty][tx] = (i0 + ty < MM) ? W[(size_t)(i0 + ty) * NN + k0 + tx] : 0.f;
        sB[ty][tx] = (j0 + ty < MM) ? W[(size_t)(j0 + ty) * NN + k0 + tx] : 0.f;
        __syncthreads();
#pragma unroll
        for (int kk = 0; kk < 16; kk++) acc += sA[ty][kk] * sB[tx][kk];
        __syncthreads();
    }
    int i = i0 + ty, j = j0 + tx;
    if (i < MM && j < MM) C[i * MM + j] = acc - (i == j ? 1.f : 0.f);
}

// ---------------- elementwise ----------------

__global__ void k_layer0(const float* __restrict__ PhiTb, float* __restrict__ X1,
                         float* __restrict__ zf,
                         const float* __restrict__ h_arr, const float* __restrict__ b2_arr)
{
    int i = blockIdx.x * blockDim.x + threadIdx.x;
    if (i >= NB) return;
    float h0 = h_arr[0], b2 = b2_arr[0];
    float x = h0 * PhiTb[i];
    X1[i] = x;
    zf[i] = h0 * b2 * x;
}

__global__ void k_hatx(const float* __restrict__ Xc, const float* __restrict__ Xp,
                       float* __restrict__ hx,
                       const float* __restrict__ tx_arr, int layer)
{
    int i = blockIdx.x * blockDim.x + threadIdx.x;
    if (i >= NB) return;
    float t = tx_arr[layer];
    float xc = Xc[i];
    hx[i] = xc + t * (xc - Xp[i]);
}

__global__ void k_xepi(const float* __restrict__ hx, const float* __restrict__ gm,
                       const float* __restrict__ PhiTb,
                       const float* __restrict__ Zg, const float* __restrict__ Lg,
                       const float* __restrict__ Zc, const float* __restrict__ Zp,
                       const float* __restrict__ Lz,
                       float* __restrict__ Xn, float* __restrict__ zf,
                       const float* __restrict__ b1a, const float* __restrict__ b2a,
                       const float* __restrict__ ha, const float* __restrict__ tza,
                       int layer)
{
    int i = blockIdx.x * blockDim.x + threadIdx.x;
    if (i >= NB) return;
    float b1 = b1a[layer], b2 = b2a[layer], hh = ha[layer], tz = tza[layer];
    float hxv = hx[i];
    float grad = PhiTb[i] - gm[i] + b1 * (Zg[i] - hxv) - Lg[i];
    float xn = hxv + hh * grad;
    Xn[i] = xn;
    float zc = Zc[i];
    float hz = zc + tz * (zc - Zp[i]);
    zf[i] = hz + hh * (Lz[i] + b2 * (xn - hz));
}

// ---------------- convolutions ----------------

// 1->32 channels, 3x3 SAME, relu. One block per image.
__global__ __launch_bounds__(256) void conv1to32(const float* __restrict__ zf,
                                                 const float* __restrict__ w,
                                                 float* __restrict__ out)
{
    __shared__ float sIn[PADSZ];
    __shared__ float sW[288];
    int img = blockIdx.x, tid = threadIdx.x;
    for (int i = tid; i < PADSZ; i += 256) sIn[i] = 0.f;
    for (int i = tid; i < 288; i += 256) sW[i] = w[i];
    __syncthreads();
    const float* gin = zf + (size_t)img * NN;
    for (int i = tid; i < NN; i += 256) {
        int r = i / 40, c = i - r * 40;
        sIn[(r + 1) * PADC + c + 1] = gin[i];
    }
    __syncthreads();
    float* gout = out + (size_t)img * FEAT_STRIDE;
    for (int i = tid; i < FEAT_STRIDE; i += 256) {
        int oc = i / 800;
        int p = i - oc * 800;
        int r = p / 40, c = p - r * 40;
        const float* w9 = sW + oc * 9;
        const float* ib = sIn + r * PADC + c;
        float a = 0.f;
#pragma unroll
        for (int dd = 0; dd < 3; dd++) {
            a += w9[dd * 3 + 0] * ib[dd * PADC + 0];
            a += w9[dd * 3 + 1] * ib[dd * PADC + 1];
            a += w9[dd * 3 + 2] * ib[dd * PADC + 2];
        }
        gout[i] = fmaxf(a, 0.f);
    }
}

// 32->32 channels, 3x3 SAME. Optional soft-threshold on input, relu on output.
// One block per image, 512 threads. Dynamic smem: padded input + weights.
__global__ __launch_bounds__(512) void conv32to32(const float* __restrict__ in,
                                                  const float* __restrict__ wts,
                                                  float* __restrict__ out,
                                                  const float* __restrict__ thr_arr,
                                                  int layer, int do_soft, int do_relu)
{
    extern __shared__ float smem[];
    float* sIn = smem;               // 32*968
    float* sW = smem + 32 * PADSZ;   // 9216
    int img = blockIdx.x, tid = threadIdx.x;
    const float* gin = in + (size_t)img * FEAT_STRIDE;

    for (int i = tid; i < 32 * PADSZ; i += 512) sIn[i] = 0.f;
    for (int i = tid; i < 9216; i += 512) sW[i] = wts[i];
    __syncthreads();

    float sthr = 0.f;
    if (do_soft) sthr = fabsf(thr_arr[layer]);

    for (int i = tid; i < 6400; i += 512) {
        float4 v = ((const float4*)gin)[i];
        int p = i * 4;
#pragma unroll
        for (int j = 0; j < 4; j++) {
            float x = (&v.x)[j];
            if (do_soft) {
                float a = fabsf(x) - sthr;
                x = (a > 0.f) ? (x > 0.f ? a : -a) : 0.f;
            }
            int pp = p + j;
            int ic = pp / 800;
            int pix = pp - ic * 800;
            int r = pix / 40;
            int c = pix - r * 40;
            sIn[ic * PADSZ + (r + 1) * PADC + (c + 1)] = x;
        }
    }
    __syncthreads();

    float* gout = out + (size_t)img * FEAT_STRIDE;
#pragma unroll
    for (int it = 0; it < 5; it++) {
        int cidx = tid + it * 512;          // 0..2559
        int oc = cidx / 80;
        int rc = cidx - oc * 80;
        int row = rc >> 2;
        int col0 = (rc & 3) * 10;
        float acc[10];
#pragma unroll
        for (int j = 0; j < 10; j++) acc[j] = 0.f;
        const float* wb = sW + oc * 288;
#pragma unroll 4
        for (int ic = 0; ic < 32; ic++) {
            const float* w9 = wb + ic * 9;
            const float* ib = sIn + ic * PADSZ + row * PADC + col0;
#pragma unroll
            for (int dd = 0; dd < 3; dd++) {
                float w0 = w9[dd * 3 + 0], w1 = w9[dd * 3 + 1], w2 = w9[dd * 3 + 2];
                const float* rp = ib + dd * PADC;
                float x0 = rp[0], x1 = rp[1];
#pragma unroll
                for (int j = 0; j < 10; j++) {
                    float x2 = rp[j + 2];
                    acc[j] += w0 * x0;
                    acc[j] += w1 * x1;
                    acc[j] += w2 * x2;
                    x0 = x1; x1 = x2;
                }
            }
        }
        float* ob = gout + oc * 800 + row * 40 + col0;
#pragma unroll
        for (int j = 0; j < 10; j++) {
            float v = acc[j];
            if (do_relu) v = fmaxf(v, 0.f);
            ob[j] = v;
        }
    }
}

// 32->1 channels, 3x3 SAME. variant 0: write Z_new and fused L-update.
// variant 1: write (conv - z_flat) into syms.
__global__ __launch_bounds__(256) void conv32to1(const float* __restrict__ in,
                                                 const float* __restrict__ w288,
                                                 float* __restrict__ outp,
                                                 const float* __restrict__ zf,
                                                 float* __restrict__ Ln,
                                                 const float* __restrict__ Lc,
                                                 const float* __restrict__ Lp,
                                                 const float* __restrict__ Xn,
                                                 const float* __restrict__ h_arr,
                                                 const float* __restrict__ b1_arr,
                                                 const float* __restrict__ tL_arr,
                                                 int layer, int variant)
{
    extern __shared__ float smem[];
    float* sIn = smem;
    float* sW = smem + 32 * PADSZ;
    int img = blockIdx.x, tid = threadIdx.x;
    const float* gin = in + (size_t)img * FEAT_STRIDE;
    for (int i = tid; i < 32 * PADSZ; i += 256) sIn[i] = 0.f;
    for (int i = tid; i < 288; i += 256) sW[i] = w288[i];
    __syncthreads();
    for (int i = tid; i < 6400; i += 256) {
        float4 v = ((const float4*)gin)[i];
        int p = i * 4;
#pragma unroll
        for (int j = 0; j < 4; j++) {
            int pp = p + j;
            int ic = pp / 800;
            int pix = pp - ic * 800;
            int r = pix / 40;
            int c = pix - r * 40;
            sIn[ic * PADSZ + (r + 1) * PADC + (c + 1)] = (&v.x)[j];
        }
    }
    __syncthreads();
    size_t base = (size_t)img * NN;
    for (int p = tid; p < NN; p += 256) {
        int r = p / 40, c = p - r * 40;
        float a = 0.f;
#pragma unroll 8
        for (int ic = 0; ic < 32; ic++) {
            const float* w9 = sW + ic * 9;
            const float* ib = sIn + ic * PADSZ + r * PADC + c;
#pragma unroll
            for (int dd = 0; dd < 3; dd++) {
                a += w9[dd * 3 + 0] * ib[dd * PADC + 0];
                a += w9[dd * 3 + 1] * ib[dd * PADC + 1];
                a += w9[dd * 3 + 2] * ib[dd * PADC + 2];
            }
        }
        if (variant == 0) {
            outp[base + p] = a;
            float lc = Lc[base + p], lp = Lp[base + p];
            float hatL = lc + tL_arr[layer] * (lc - lp);
            Ln[base + p] = hatL + h_arr[layer] * b1_arr[layer] * (Xn[base + p] - a);
        } else {
            outp[base + p] = a - zf[base + p];
        }
    }
}

// ---------------- host ----------------

extern "C" void kernel_launch(void* const* d_in, const int* in_sizes, int n_in,
                              void* d_out, int out_size)
{
    const float* y    = (const float*)d_in[0];
    const float* W    = (const float*)d_in[2];
    const float* beta1 = (const float*)d_in[3];
    const float* beta2 = (const float*)d_in[4];
    const float* h_   = (const float*)d_in[5];
    const float* sthr = (const float*)d_in[6];
    const float* thx  = (const float*)d_in[7];
    const float* thz  = (const float*)d_in[8];
    const float* thL  = (const float*)d_in[9];
    const float* c1f  = (const float*)d_in[10];
    const float* c2f  = (const float*)d_in[11];
    const float* c1b  = (const float*)d_in[12];
    const float* c2b  = (const float*)d_in[13];

    float* out = (float*)d_out;
    float* Zs = out;
    float* syms = out + (size_t)9 * NB;
    float* wlo = out + (size_t)18 * NB;

    float *pPhiTPhi, *pPhiTb, *pX, *pL, *pZero, *pZf, *pHx, *pGm, *pFA, *pFB;
    cudaGetSymbolAddress((void**)&pPhiTPhi, g_PhiTPhi);
    cudaGetSymbolAddress((void**)&pPhiTb, g_PhiTb);
    cudaGetSymbolAddress((void**)&pX, g_Xbuf);
    cudaGetSymbolAddress((void**)&pL, g_Lbuf);
    cudaGetSymbolAddress((void**)&pZero, g_zerobuf);
    cudaGetSymbolAddress((void**)&pZf, g_zflat);
    cudaGetSymbolAddress((void**)&pHx, g_hatx);
    cudaGetSymbolAddress((void**)&pGm, g_gemm);
    cudaGetSymbolAddress((void**)&pFA, g_fA);
    cudaGetSymbolAddress((void**)&pFB, g_fB);

    const int SM32 = (32 * PADSZ + 9216) * 4;   // 160,768 B
    const int SM1 = (32 * PADSZ + 288) * 4;     // 125,056 B
    cudaFuncSetAttribute(conv32to32, cudaFuncAttributeMaxDynamicSharedMemorySize, SM32);
    cudaFuncSetAttribute(conv32to1, cudaFuncAttributeMaxDynamicSharedMemorySize, SM1);

    cudaMemsetAsync(pZero, 0, (size_t)NB * 4);

    float* Xslot[2] = {pX, pX + NB};
    float* Lslot[2] = {pL, pL + NB};

    // setup
    gemm_AtB<<<dim3(13, 13), 256>>>(W, W, pPhiTPhi, MM, NN, NN);
    k_wloss<<<dim3(21, 21), dim3(16, 16)>>>(W, wlo);
    gemm_AB<<<dim3(13, 64), 256>>>(y, W, pPhiTb, BB, MM, NN);

    int xcur = 0, xprev = -1;
    int lcur = 0, lprev = -1;

    for (int i = 0; i < 9; i++) {
        float* Xn;
        if (i == 0) {
            Xn = Xslot[0];
            k_layer0<<<NB / 256, 256>>>(pPhiTb, Xn, pZf, h_, beta2);
            xcur = 0; xprev = -1;
        } else {
            const float* Xc = Xslot[xcur];
            const float* Xp = (xprev < 0) ? pZero : Xslot[xprev];
            const float* Lc_ = Lslot[lcur];
            const float* Zc = Zs + (size_t)(i - 1) * NB;
            const float* Zp = (i >= 2) ? Zs + (size_t)(i - 2) * NB : pZero;
            const float* Zg = (i >= 2) ? Zc : pZero;
            const float* Lg = (i >= 2) ? Lc_ : pZero;
            const float* Lz = (i >= 2) ? Lc_ : pZero;
            int xnew = (xprev < 0) ? 1 : xprev;
            Xn = Xslot[xnew];
            k_hatx<<<NB / 256, 256>>>(Xc, Xp, pHx, thx, i);
            gemm_AB<<<dim3(13, 64), 256>>>(pHx, pPhiTPhi, pGm, BB, NN, NN);
            k_xepi<<<NB / 256, 256>>>(pHx, pGm, pPhiTb, Zg, Lg, Zc, Zp, Lz,
                                      Xn, pZf, beta1, beta2, h_, thz, i);
            xprev = xcur; xcur = xnew;
        }

        // conv block
        conv1to32<<<BB, 256>>>(pZf, c1f, pFA);
        conv32to32<<<BB, 512, SM32>>>(pFA, c2f, pFB, sthr, i, 0, 0);          // x_fwd
        conv32to32<<<BB, 512, SM32>>>(pFB, c1b, pFA, sthr, i, 1, 1);          // t1
        {
            const float* Lc_ = (i == 0) ? pZero : Lslot[lcur];
            const float* Lp_ = (i == 0) ? pZero : ((lprev < 0) ? pZero : Lslot[lprev]);
            int lnew = (i == 0) ? 0 : ((lprev < 0) ? 1 : lprev);
            conv32to1<<<BB, 256, SM1>>>(pFA, c2b, Zs + (size_t)i * NB, nullptr,
                                        Lslot[lnew], Lc_, Lp_, Xn,
                                        h_, beta1, thL, i, 0);
            if (i > 0) { lprev = lcur; lcur = lnew; }
            else { lcur = 0; lprev = -1; }
        }
        conv32to32<<<BB, 512, SM32>>>(pFB, c1b, pFA, sthr, i, 0, 1);          // t2
        conv32to1<<<BB, 256, SM1>>>(pFA, c2b, syms + (size_t)i * NB, pZf,
                                    nullptr, nullptr, nullptr, nullptr,
                                    h_, beta1, thL, i, 1);
    }
}

// round 4
// speedup vs baseline: 1.9053x; 1.9053x over previous
#include <cuda_runtime.h>
#include <cuda_bf16.h>
#include <cstdint>

#define BB 4096
#define MM 327
#define NN 800
#define NB (BB*NN)              // 3,276,800 per state buffer
#define FEAT (BB*32*NN)         // 104,857,600 per feature buffer
#define FEAT_STRIDE (32*NN)     // 25600 per image
#define PADC 44
#define PADSZ (22*44)           // 968 floats per padded channel

// ---------------- device scratch (static, allowed) ----------------
__device__ float g_PhiTPhi[NN*NN];
__device__ float g_PhiTb[NB];
__device__ float g_Xbuf[2*NB];
__device__ float g_Lbuf[2*NB];
__device__ float g_zerobuf[NB];
__device__ float g_zflat[NB];
__device__ float g_hatx[NB];
__device__ float g_gemm[NB];
__device__ float g_fA[FEAT];
__device__ float g_fB[FEAT];

// ---------------- small GEMMs ----------------

// C[I,J] = sum_k A[k,i] * B[k,j]   (A,B row-major [K, ld]); used for PhiTPhi = W^T W
__global__ __launch_bounds__(256) void gemm_AtB(const float* __restrict__ A,
                                                const float* __restrict__ B,
                                                float* __restrict__ C,
                                                int K, int I, int J)
{
    __shared__ float As[16][68];
    __shared__ float Bs[16][68];
    int tid = threadIdx.x;
    int tx = tid & 15, ty = tid >> 4;
    int i0 = blockIdx.y * 64, j0 = blockIdx.x * 64;
    float acc[4][4];
#pragma unroll
    for (int a = 0; a < 4; a++)
#pragma unroll
        for (int b = 0; b < 4; b++) acc[a][b] = 0.f;

    int kr = tid >> 4, c4 = (tid & 15) * 4;
    for (int k0 = 0; k0 < K; k0 += 16) {
        bool kv = (k0 + kr) < K;
#pragma unroll
        for (int j = 0; j < 4; j++) {
            int ii = i0 + c4 + j;
            As[kr][c4 + j] = (kv && ii < I) ? A[(size_t)(k0 + kr) * I + ii] : 0.f;
            int jj = j0 + c4 + j;
            Bs[kr][c4 + j] = (kv && jj < J) ? B[(size_t)(k0 + kr) * J + jj] : 0.f;
        }
        __syncthreads();
#pragma unroll
        for (int kk = 0; kk < 16; kk++) {
            float a[4], b[4];
#pragma unroll
            for (int i = 0; i < 4; i++) a[i] = As[kk][ty * 4 + i];
#pragma unroll
            for (int j = 0; j < 4; j++) b[j] = Bs[kk][tx * 4 + j];
#pragma unroll
            for (int i = 0; i < 4; i++)
#pragma unroll
                for (int j = 0; j < 4; j++) acc[i][j] += a[i] * b[j];
        }
        __syncthreads();
    }
#pragma unroll
    for (int i = 0; i < 4; i++) {
        int r = i0 + ty * 4 + i;
        if (r < I) {
#pragma unroll
            for (int j = 0; j < 4; j++) {
                int n = j0 + tx * 4 + j;
                if (n < J) C[(size_t)r * J + n] = acc[i][j];
            }
        }
    }
}

// C[M,N] = A[M,K] * B[K,N]  (row-major). M must be multiple of 128.
// 128x64 block tile, 256 threads, 8x4 microtile.
__global__ __launch_bounds__(256) void gemm_AB(const float* __restrict__ A,
                                               const float* __restrict__ B,
                                               float* __restrict__ C,
                                               int M, int K, int N)
{
    __shared__ float As[16][132];   // [k][row]
    __shared__ float Bs[16][68];    // [k][col]
    int tid = threadIdx.x;
    int tx = tid & 15, ty = tid >> 4;
    int row0 = blockIdx.y * 128, n0 = blockIdx.x * 64;

    float acc[8][4];
#pragma unroll
    for (int a = 0; a < 8; a++)
#pragma unroll
        for (int b = 0; b < 4; b++) acc[a][b] = 0.f;

    int arow = tid >> 1;            // 0..127
    int ak0 = (tid & 1) * 8;        // 0 or 8
    int kr = tid >> 4, nc = (tid & 15) * 4;

    for (int k0 = 0; k0 < K; k0 += 16) {
        const float* aptr = A + (size_t)(row0 + arow) * K + k0 + ak0;
#pragma unroll
        for (int j = 0; j < 8; j++) {
            int k = k0 + ak0 + j;
            As[ak0 + j][arow] = (k < K) ? aptr[j] : 0.f;
        }
#pragma unroll
        for (int j = 0; j < 4; j++) {
            int n = n0 + nc + j;
            Bs[kr][nc + j] = ((k0 + kr) < K && n < N) ? B[(size_t)(k0 + kr) * N + n] : 0.f;
        }
        __syncthreads();
#pragma unroll
        for (int kk = 0; kk < 16; kk++) {
            float a[8], b[4];
#pragma unroll
            for (int i = 0; i < 8; i++) a[i] = As[kk][ty * 8 + i];
#pragma unroll
            for (int j = 0; j < 4; j++) b[j] = Bs[kk][tx * 4 + j];
#pragma unroll
            for (int i = 0; i < 8; i++)
#pragma unroll
                for (int j = 0; j < 4; j++) acc[i][j] += a[i] * b[j];
        }
        __syncthreads();
    }
#pragma unroll
    for (int i = 0; i < 8; i++) {
        int r = row0 + ty * 8 + i;
#pragma unroll
        for (int j = 0; j < 4; j++) {
            int n = n0 + tx * 4 + j;
            if (n < N) C[(size_t)r * N + n] = acc[i][j];
        }
    }
}

// Wloss = W @ W^T - I, [327,327], K=800
__global__ void k_wloss(const float* __restrict__ W, float* __restrict__ C)
{
    __shared__ float sA[16][17];
    __shared__ float sB[16][17];
    int tx = threadIdx.x, ty = threadIdx.y;
    int i0 = blockIdx.y * 16, j0 = blockIdx.x * 16;
    float acc = 0.f;
    for (int k0 = 0; k0 < 800; k0 += 16) {
        sA[ty][tx] = (i0 + ty < MM) ? W[(size_t)(i0 + ty) * NN + k0 + tx] : 0.f;
        sB[ty][tx] = (j0 + ty < MM) ? W[(size_t)(j0 + ty) * NN + k0 + tx] : 0.f;
        __syncthreads();
#pragma unroll
        for (int kk = 0; kk < 16; kk++) acc += sA[ty][kk] * sB[tx][kk];
        __syncthreads();
    }
    int i = i0 + ty, j = j0 + tx;
    if (i < MM && j < MM) C[i * MM + j] = acc - (i == j ? 1.f : 0.f);
}

// ---------------- elementwise ----------------

__global__ void k_layer0(const float* __restrict__ PhiTb, float* __restrict__ X1,
                         float* __restrict__ zf,
                         const float* __restrict__ h_arr, const float* __restrict__ b2_arr)
{
    int i = blockIdx.x * blockDim.x + threadIdx.x;
    if (i >= NB) return;
    float h0 = h_arr[0], b2 = b2_arr[0];
    float x = h0 * PhiTb[i];
    X1[i] = x;
    zf[i] = h0 * b2 * x;
}

__global__ void k_hatx(const float* __restrict__ Xc, const float* __restrict__ Xp,
                       float* __restrict__ hx,
                       const float* __restrict__ tx_arr, int layer)
{
    int i = blockIdx.x * blockDim.x + threadIdx.x;
    if (i >= NB) return;
    float t = tx_arr[layer];
    float xc = Xc[i];
    hx[i] = xc + t * (xc - Xp[i]);
}

__global__ void k_xepi(const float* __restrict__ hx, const float* __restrict__ gm,
                       const float* __restrict__ PhiTb,
                       const float* __restrict__ Zg, const float* __restrict__ Lg,
                       const float* __restrict__ Zc, const float* __restrict__ Zp,
                       const float* __restrict__ Lz,
                       float* __restrict__ Xn, float* __restrict__ zf,
                       const float* __restrict__ b1a, const float* __restrict__ b2a,
                       const float* __restrict__ ha, const float* __restrict__ tza,
                       int layer)
{
    int i = blockIdx.x * blockDim.x + threadIdx.x;
    if (i >= NB) return;
    float b1 = b1a[layer], b2 = b2a[layer], hh = ha[layer], tz = tza[layer];
    float hxv = hx[i];
    float grad = PhiTb[i] - gm[i] + b1 * (Zg[i] - hxv) - Lg[i];
    float xn = hxv + hh * grad;
    Xn[i] = xn;
    float zc = Zc[i];
    float hz = zc + tz * (zc - Zp[i]);
    zf[i] = hz + hh * (Lz[i] + b2 * (xn - hz));
}

// ---------------- convolutions ----------------

// 1->32 channels, 3x3 SAME, relu. One block per image.
__global__ __launch_bounds__(256) void conv1to32(const float* __restrict__ zf,
                                                 const float* __restrict__ w,
                                                 float* __restrict__ out)
{
    __shared__ float sIn[PADSZ];
    __shared__ float sW[288];
    int img = blockIdx.x, tid = threadIdx.x;
    for (int i = tid; i < PADSZ; i += 256) sIn[i] = 0.f;
    for (int i = tid; i < 288; i += 256) sW[i] = w[i];
    __syncthreads();
    const float* gin = zf + (size_t)img * NN;
    for (int i = tid; i < NN; i += 256) {
        int r = i / 40, c = i - r * 40;
        sIn[(r + 1) * PADC + c + 1] = gin[i];
    }
    __syncthreads();
    float* gout = out + (size_t)img * FEAT_STRIDE;
    for (int i = tid; i < FEAT_STRIDE; i += 256) {
        int oc = i / 800;
        int p = i - oc * 800;
        int r = p / 40, c = p - r * 40;
        const float* w9 = sW + oc * 9;
        const float* ib = sIn + r * PADC + c;
        float a = 0.f;
#pragma unroll
        for (int dd = 0; dd < 3; dd++) {
            a += w9[dd * 3 + 0] * ib[dd * PADC + 0];
            a += w9[dd * 3 + 1] * ib[dd * PADC + 1];
            a += w9[dd * 3 + 2] * ib[dd * PADC + 2];
        }
        gout[i] = fmaxf(a, 0.f);
    }
}

// 32->32 channels, 3x3 SAME. Optional soft-threshold on input, relu on output.
// One block per image, 640 threads; each thread computes 4 oc x 10 px.
__global__ __launch_bounds__(640) void conv32to32(const float* __restrict__ in,
                                                  const float* __restrict__ wts,
                                                  float* __restrict__ out,
                                                  const float* __restrict__ thr_arr,
                                                  int layer, int do_soft, int do_relu)
{
    extern __shared__ float smem[];
    float* sIn = smem;               // 32*968
    float* sW = smem + 32 * PADSZ;   // 9216
    int img = blockIdx.x, tid = threadIdx.x;
    const float* gin = in + (size_t)img * FEAT_STRIDE;

    for (int i = tid; i < 32 * PADSZ; i += 640) sIn[i] = 0.f;
    for (int i = tid; i < 9216; i += 640) sW[i] = wts[i];
    __syncthreads();

    float sthr = 0.f;
    if (do_soft) sthr = fabsf(thr_arr[layer]);

    for (int i = tid; i < 6400; i += 640) {
        float4 v = ((const float4*)gin)[i];
        int p = i * 4;
#pragma unroll
        for (int j = 0; j < 4; j++) {
            float x = (&v.x)[j];
            if (do_soft) {
                float a = fabsf(x) - sthr;
                x = (a > 0.f) ? (x > 0.f ? a : -a) : 0.f;
            }
            int pp = p + j;
            int ic = pp / 800;
            int pix = pp - ic * 800;
            int r = pix / 40;
            int c = pix - r * 40;
            sIn[ic * PADSZ + (r + 1) * PADC + (c + 1)] = x;
        }
    }
    __syncthreads();

    // unit mapping: 8 oc-groups (4 oc each) x 20 rows x 4 col-chunks (10 px)
    int ocg = tid / 80;              // 0..7
    int rc = tid - ocg * 80;         // 0..79
    int row = rc >> 2;               // 0..19
    int col0 = (rc & 3) * 10;        // 0,10,20,30
    int oc0 = ocg * 4;

    float acc[4][10];
#pragma unroll
    for (int q = 0; q < 4; q++)
#pragma unroll
        for (int j = 0; j < 10; j++) acc[q][j] = 0.f;

    const float* wb = sW + oc0 * 288;
    const float* ibase = sIn + row * PADC + col0;

    for (int ic = 0; ic < 32; ic++) {
        const float* w9 = wb + ic * 9;
        const float* ib = ibase + ic * PADSZ;
#pragma unroll
        for (int dd = 0; dd < 3; dd++) {
            const float* rp = ib + dd * PADC;
            float x[12];
#pragma unroll
            for (int j = 0; j < 12; j++) x[j] = rp[j];
            float w0[4], w1[4], w2[4];
#pragma unroll
            for (int q = 0; q < 4; q++) {
                w0[q] = w9[q * 288 + dd * 3 + 0];
                w1[q] = w9[q * 288 + dd * 3 + 1];
                w2[q] = w9[q * 288 + dd * 3 + 2];
            }
#pragma unroll
            for (int q = 0; q < 4; q++)
#pragma unroll
                for (int j = 0; j < 10; j++) {
                    acc[q][j] += w0[q] * x[j];
                    acc[q][j] += w1[q] * x[j + 1];
                    acc[q][j] += w2[q] * x[j + 2];
                }
        }
    }

    float* gout = out + (size_t)img * FEAT_STRIDE + row * 40 + col0;
#pragma unroll
    for (int q = 0; q < 4; q++) {
        float* ob = gout + (oc0 + q) * 800;
#pragma unroll
        for (int j = 0; j < 10; j++) {
            float v = acc[q][j];
            if (do_relu) v = fmaxf(v, 0.f);
            ob[j] = v;
        }
    }
}

// 32->1 channels, 3x3 SAME. variant 0: write Z_new and fused L-update.
// variant 1: write (conv - z_flat) into syms.
__global__ __launch_bounds__(256) void conv32to1(const float* __restrict__ in,
                                                 const float* __restrict__ w288,
                                                 float* __restrict__ outp,
                                                 const float* __restrict__ zf,
                                                 float* __restrict__ Ln,
                                                 const float* __restrict__ Lc,
                                                 const float* __restrict__ Lp,
                                                 const float* __restrict__ Xn,
                                                 const float* __restrict__ h_arr,
                                                 const float* __restrict__ b1_arr,
                                                 const float* __restrict__ tL_arr,
                                                 int layer, int variant)
{
    extern __shared__ float smem[];
    float* sIn = smem;
    float* sW = smem + 32 * PADSZ;
    int img = blockIdx.x, tid = threadIdx.x;
    const float* gin = in + (size_t)img * FEAT_STRIDE;
    for (int i = tid; i < 32 * PADSZ; i += 256) sIn[i] = 0.f;
    for (int i = tid; i < 288; i += 256) sW[i] = w288[i];
    __syncthreads();
    for (int i = tid; i < 6400; i += 256) {
        float4 v = ((const float4*)gin)[i];
        int p = i * 4;
#pragma unroll
        for (int j = 0; j < 4; j++) {
            int pp = p + j;
            int ic = pp / 800;
            int pix = pp - ic * 800;
            int r = pix / 40;
            int c = pix - r * 40;
            sIn[ic * PADSZ + (r + 1) * PADC + (c + 1)] = (&v.x)[j];
        }
    }
    __syncthreads();
    size_t base = (size_t)img * NN;
    for (int p = tid; p < NN; p += 256) {
        int r = p / 40, c = p - r * 40;
        float a = 0.f;
#pragma unroll 8
        for (int ic = 0; ic < 32; ic++) {
            const float* w9 = sW + ic * 9;
            const float* ib = sIn + ic * PADSZ + r * PADC + c;
#pragma unroll
            for (int dd = 0; dd < 3; dd++) {
                a += w9[dd * 3 + 0] * ib[dd * PADC + 0];
                a += w9[dd * 3 + 1] * ib[dd * PADC + 1];
                a += w9[dd * 3 + 2] * ib[dd * PADC + 2];
            }
        }
        if (variant == 0) {
            outp[base + p] = a;
            float lc = Lc[base + p], lp = Lp[base + p];
            float hatL = lc + tL_arr[layer] * (lc - lp);
            Ln[base + p] = hatL + h_arr[layer] * b1_arr[layer] * (Xn[base + p] - a);
        } else {
            outp[base + p] = a - zf[base + p];
        }
    }
}

// ---------------- host ----------------

extern "C" void kernel_launch(void* const* d_in, const int* in_sizes, int n_in,
                              void* d_out, int out_size)
{
    const float* y    = (const float*)d_in[0];
    const float* W    = (const float*)d_in[2];
    const float* beta1 = (const float*)d_in[3];
    const float* beta2 = (const float*)d_in[4];
    const float* h_   = (const float*)d_in[5];
    const float* sthr = (const float*)d_in[6];
    const float* thx  = (const float*)d_in[7];
    const float* thz  = (const float*)d_in[8];
    const float* thL  = (const float*)d_in[9];
    const float* c1f  = (const float*)d_in[10];
    const float* c2f  = (const float*)d_in[11];
    const float* c1b  = (const float*)d_in[12];
    const float* c2b  = (const float*)d_in[13];

    float* out = (float*)d_out;
    float* Zs = out;
    float* syms = out + (size_t)9 * NB;
    float* wlo = out + (size_t)18 * NB;

    float *pPhiTPhi, *pPhiTb, *pX, *pL, *pZero, *pZf, *pHx, *pGm, *pFA, *pFB;
    cudaGetSymbolAddress((void**)&pPhiTPhi, g_PhiTPhi);
    cudaGetSymbolAddress((void**)&pPhiTb, g_PhiTb);
    cudaGetSymbolAddress((void**)&pX, g_Xbuf);
    cudaGetSymbolAddress((void**)&pL, g_Lbuf);
    cudaGetSymbolAddress((void**)&pZero, g_zerobuf);
    cudaGetSymbolAddress((void**)&pZf, g_zflat);
    cudaGetSymbolAddress((void**)&pHx, g_hatx);
    cudaGetSymbolAddress((void**)&pGm, g_gemm);
    cudaGetSymbolAddress((void**)&pFA, g_fA);
    cudaGetSymbolAddress((void**)&pFB, g_fB);

    const int SM32 = (32 * PADSZ + 9216) * 4;   // 160,768 B
    const int SM1 = (32 * PADSZ + 288) * 4;     // 125,056 B
    cudaFuncSetAttribute(conv32to32, cudaFuncAttributeMaxDynamicSharedMemorySize, SM32);
    cudaFuncSetAttribute(conv32to1, cudaFuncAttributeMaxDynamicSharedMemorySize, SM1);

    cudaMemsetAsync(pZero, 0, (size_t)NB * 4);

    float* Xslot[2] = {pX, pX + NB};
    float* Lslot[2] = {pL, pL + NB};

    // setup
    gemm_AtB<<<dim3(13, 13), 256>>>(W, W, pPhiTPhi, MM, NN, NN);
    k_wloss<<<dim3(21, 21), dim3(16, 16)>>>(W, wlo);
    gemm_AB<<<dim3(13, 32), 256>>>(y, W, pPhiTb, BB, MM, NN);

    int xcur = 0, xprev = -1;
    int lcur = 0, lprev = -1;

    for (int i = 0; i < 9; i++) {
        float* Xn;
        if (i == 0) {
            Xn = Xslot[0];
            k_layer0<<<NB / 256, 256>>>(pPhiTb, Xn, pZf, h_, beta2);
            xcur = 0; xprev = -1;
        } else {
            const float* Xc = Xslot[xcur];
            const float* Xp = (xprev < 0) ? pZero : Xslot[xprev];
            const float* Lc_ = Lslot[lcur];
            const float* Zc = Zs + (size_t)(i - 1) * NB;
            const float* Zp = (i >= 2) ? Zs + (size_t)(i - 2) * NB : pZero;
            const float* Zg = (i >= 2) ? Zc : pZero;
            const float* Lg = (i >= 2) ? Lc_ : pZero;
            const float* Lz = (i >= 2) ? Lc_ : pZero;
            int xnew = (xprev < 0) ? 1 : xprev;
            Xn = Xslot[xnew];
            k_hatx<<<NB / 256, 256>>>(Xc, Xp, pHx, thx, i);
            gemm_AB<<<dim3(13, 32), 256>>>(pHx, pPhiTPhi, pGm, BB, NN, NN);
            k_xepi<<<NB / 256, 256>>>(pHx, pGm, pPhiTb, Zg, Lg, Zc, Zp, Lz,
                                      Xn, pZf, beta1, beta2, h_, thz, i);
            xprev = xcur; xcur = xnew;
        }

        // conv block
        conv1to32<<<BB, 256>>>(pZf, c1f, pFA);
        conv32to32<<<BB, 640, SM32>>>(pFA, c2f, pFB, sthr, i, 0, 0);          // x_fwd
        conv32to32<<<BB, 640, SM32>>>(pFB, c1b, pFA, sthr, i, 1, 1);          // t1
        {
            const float* Lc_ = (i == 0) ? pZero : Lslot[lcur];
            const float* Lp_ = (i == 0) ? pZero : ((lprev < 0) ? pZero : Lslot[lprev]);
            int lnew = (i == 0) ? 0 : ((lprev < 0) ? 1 : lprev);
            conv32to1<<<BB, 256, SM1>>>(pFA, c2b, Zs + (size_t)i * NB, nullptr,
                                        Lslot[lnew], Lc_, Lp_, Xn,
                                        h_, beta1, thL, i, 0);
            if (i > 0) { lprev = lcur; lcur = lnew; }
            else { lcur = 0; lprev = -1; }
        }
        conv32to32<<<BB, 640, SM32>>>(pFB, c1b, pFA, sthr, i, 0, 1);          // t2
        conv32to1<<<BB, 256, SM1>>>(pFA, c2b, syms + (size_t)i * NB, pZf,
                                    nullptr, nullptr, nullptr, nullptr,
                                    h_, beta1, thL, i, 1);
    }
}